// round 2
// baseline (speedup 1.0000x reference)
#include <cuda_runtime.h>

// Inputs (metadata order):
// 0: dist_mat   float32  [4096*4096]
// 1: vector_mat float32  [4096*4096*3]
// 2: forces_out float32  [4096*3]
// 3: params     float32  [N_ANGLES*2]  (k0, theta0)
// 4: coord_idx  int32    [N_ANGLES*3]  (a1, a2, a3)
// 5: calc_energy int32   [1]
// 6: calc_forces int32   [1]
// Output: out[0] = energy, out[1 .. 1+3*N_ATOMS) = forces (row-major atom,xyz)

__global__ void init_out_kernel(float* __restrict__ out,
                                const float* __restrict__ forces_in,
                                int n_forces) {
    int i = blockIdx.x * blockDim.x + threadIdx.x;
    if (i == 0) out[0] = 0.0f;
    if (i < n_forces) out[1 + i] = forces_in[i];
}

__global__ void __launch_bounds__(256) angle_kernel(
    const float* __restrict__ dist,
    const float* __restrict__ vec,
    const float* __restrict__ params,
    const int*   __restrict__ cidx,
    const int*   __restrict__ calc_e_p,
    const int*   __restrict__ calc_f_p,
    float*       __restrict__ out,
    int n_angles, int n_atoms)
{
    const int i    = blockIdx.x * blockDim.x + threadIdx.x;
    const int ce   = *calc_e_p;
    const int cf   = *calc_f_p;
    float e = 0.0f;

    if (i < n_angles) {
        const int a1 = cidx[3 * i + 0];
        const int a2 = cidx[3 * i + 1];
        const int a3 = cidx[3 * i + 2];

        const size_t r21 = (size_t)a2 * (size_t)n_atoms + (size_t)a1;
        const size_t r23 = (size_t)a2 * (size_t)n_atoms + (size_t)a3;

        const float v21x = __ldg(vec + 3 * r21 + 0);
        const float v21y = __ldg(vec + 3 * r21 + 1);
        const float v21z = __ldg(vec + 3 * r21 + 2);
        const float v23x = __ldg(vec + 3 * r23 + 0);
        const float v23y = __ldg(vec + 3 * r23 + 1);
        const float v23z = __ldg(vec + 3 * r23 + 2);
        const float d21  = __ldg(dist + r21);
        const float d23  = __ldg(dist + r23);

        const float k0 = params[2 * i + 0];
        const float t0 = params[2 * i + 1];

        float ct = v21x * v23x + v21y * v23y + v21z * v23z;
        ct = fminf(1.0f, fmaxf(-1.0f, ct));

        const float theta = acosf(ct);
        const float dth   = theta - t0;

        if (ce) e = k0 * dth * dth;

        if (cf) {
            const float st   = sqrtf(fmaxf(0.0f, 1.0f - ct * ct));
            const float coef = (st > 0.0f)
                             ? (-2.0f * k0 * dth / fmaxf(st, 1e-12f))
                             : 0.0f;
            const float c21 = coef / d21;
            const float c23 = coef / d23;

            const float f0x = c21 * (ct * v21x - v23x);
            const float f0y = c21 * (ct * v21y - v23y);
            const float f0z = c21 * (ct * v21z - v23z);
            const float f2x = c23 * (ct * v23x - v21x);
            const float f2y = c23 * (ct * v23y - v21y);
            const float f2z = c23 * (ct * v23z - v21z);
            const float f1x = -(f0x + f2x);
            const float f1y = -(f0y + f2y);
            const float f1z = -(f0z + f2z);

            float* forces = out + 1;
            atomicAdd(&forces[3 * a1 + 0], f0x);
            atomicAdd(&forces[3 * a1 + 1], f0y);
            atomicAdd(&forces[3 * a1 + 2], f0z);
            atomicAdd(&forces[3 * a2 + 0], f1x);
            atomicAdd(&forces[3 * a2 + 1], f1y);
            atomicAdd(&forces[3 * a2 + 2], f1z);
            atomicAdd(&forces[3 * a3 + 0], f2x);
            atomicAdd(&forces[3 * a3 + 1], f2y);
            atomicAdd(&forces[3 * a3 + 2], f2z);
        }
    }

    // Hierarchical energy reduction: warp shuffle -> shared -> one atomic/block.
    if (ce) {
        #pragma unroll
        for (int off = 16; off > 0; off >>= 1)
            e += __shfl_down_sync(0xffffffffu, e, off);

        __shared__ float warp_sums[8];
        const int lane = threadIdx.x & 31;
        const int wid  = threadIdx.x >> 5;
        if (lane == 0) warp_sums[wid] = e;
        __syncthreads();

        if (wid == 0) {
            e = (lane < (int)(blockDim.x >> 5)) ? warp_sums[lane] : 0.0f;
            #pragma unroll
            for (int off = 4; off > 0; off >>= 1)
                e += __shfl_down_sync(0xffffffffu, e, off);
            if (lane == 0) atomicAdd(out, e);
        }
    }
}

extern "C" void kernel_launch(void* const* d_in, const int* in_sizes, int n_in,
                              void* d_out, int out_size) {
    const float* dist   = (const float*)d_in[0];
    const float* vec    = (const float*)d_in[1];
    const float* f_in   = (const float*)d_in[2];
    const float* params = (const float*)d_in[3];
    const int*   cidx   = (const int*)  d_in[4];
    const int*   ce     = (const int*)  d_in[5];
    const int*   cf     = (const int*)  d_in[6];
    float*       out    = (float*)d_out;

    const int n_angles = in_sizes[4] / 3;
    const int n_forces = in_sizes[2];          // 3 * N_ATOMS
    const int n_atoms  = n_forces / 3;

    {
        const int threads = 256;
        const int blocks  = (n_forces + threads) / threads; // covers energy slot too
        init_out_kernel<<<blocks, threads>>>(out, f_in, n_forces);
    }
    {
        const int threads = 256;
        const int blocks  = (n_angles + threads - 1) / threads;
        angle_kernel<<<blocks, threads>>>(dist, vec, params, cidx, ce, cf,
                                          out, n_angles, n_atoms);
    }
}